// round 2
// baseline (speedup 1.0000x reference)
#include <cuda_runtime.h>
#include <math.h>

// Problem constants
#define B_      512
#define T_      128
#define V_      36
#define E_      128
#define H_      512
#define FOURH   2048
#define TSTEPS  127
#define IGN     0

// Output layout (concatenated, float32): probs [B,T-1,V] | emb [B,T,E] | sample_loss [B] | mean [1]
#define PROBS_N  ((size_t)B_ * TSTEPS * V_)          // 2,340,864
#define EMB_N    ((size_t)B_ * T_ * E_)              // 8,388,608
#define OFF_PROBS 0
#define OFF_EMB   (PROBS_N)
#define OFF_SL    (OFF_EMB + EMB_N)
#define OFF_MEAN  (OFF_SL + B_)

// ---------------- scratch (static device globals; no allocation) ----------------
__device__ float g_Wcat0[640 * FOURH];    // [k][n]: rows 0..127 = W_ih0^T, 128..639 = W_hh0^T   (5 MB)
__device__ float g_Wcat1[1024 * FOURH];   // [k][n]: rows 0..511 = W_ih1^T, 512..1023 = W_hh1^T  (8 MB)
__device__ float g_bias0[FOURH];          // b_ih0 + b_hh0
__device__ float g_bias1v[FOURH];         // b_ih1 + b_hh1
__device__ float g_G[B_ * FOURH];         // pre-activation gates for current layer (4 MB)
__device__ float g_HH[B_ * 1024];         // per batch row: [h0 (512) | h1 (512)]  (2 MB)
__device__ float g_c0[B_ * H_];
__device__ float g_c1[B_ * H_];
__device__ float g_loss[B_ * TSTEPS];

// ---------------- prologue: weight repack + state zero ----------------
__global__ void prep_kernel(const float* __restrict__ Wih0, const float* __restrict__ Whh0,
                            const float* __restrict__ Wih1, const float* __restrict__ Whh1,
                            const float* __restrict__ bi0,  const float* __restrict__ bh0,
                            const float* __restrict__ bi1,  const float* __restrict__ bh1) {
    int i = blockIdx.x * 256 + threadIdx.x;
    if (i < 1024 * FOURH) {                   // Wcat1
        int k = i >> 11, n = i & 2047;
        g_Wcat1[i] = (k < 512) ? Wih1[n * 512 + k] : Whh1[n * 512 + (k - 512)];
    }
    if (i < 640 * FOURH) {                    // Wcat0
        int k = i >> 11, n = i & 2047;
        g_Wcat0[i] = (k < 128) ? Wih0[n * 128 + k] : Whh0[n * 512 + (k - 128)];
    }
    if (i < B_ * 1024) g_HH[i] = 0.f;
    if (i < B_ * H_)   { g_c0[i] = 0.f; g_c1[i] = 0.f; }
    if (i < FOURH)     { g_bias0[i] = bi0[i] + bh0[i]; g_bias1v[i] = bi1[i] + bh1[i]; }
}

// ---------------- embedding output (float4 vectorized) ----------------
__global__ void embed_kernel(const int* __restrict__ x, const float* __restrict__ tab,
                             float* __restrict__ out_emb) {
    int idx = blockIdx.x * 256 + threadIdx.x;           // over B*T*E/4
    if (idx >= (int)(EMB_N / 4)) return;
    int e4 = idx & 31;                                  // E/4 = 32
    int bt = idx >> 5;
    int tok = x[bt];
    float4 v = reinterpret_cast<const float4*>(tab)[tok * 32 + e4];
    reinterpret_cast<float4*>(out_emb)[idx] = v;
}

// ---------------- fused step GEMM: G = bias + A @ Wcat ----------------
// which==1: A row b = [emb_table[x[b,t]] (128) | h0 (512)],  K=640,  B=Wcat0
// which==2: A row b = [h0 (512) | h1 (512)],                 K=1024, B=Wcat1
// M=512, N=2048. BM=BN=64, BK=16, 256 threads, 4x4 microtile. Grid (32, 8).
#define GBM 64
#define GBN 64
#define GBK 16

__global__ __launch_bounds__(256) void gemm_step_kernel(int which, int t,
                                                        const int* __restrict__ x,
                                                        const float* __restrict__ emb_table) {
    __shared__ float As[GBK][GBM];
    __shared__ float Bs[GBK][GBN];
    __shared__ int tokens[GBM];

    const float* Bmat;
    const float* bias;
    int K;
    if (which == 1) { Bmat = g_Wcat0; bias = g_bias0;  K = 640;  }
    else            { Bmat = g_Wcat1; bias = g_bias1v; K = 1024; }

    const int row0 = blockIdx.y * GBM;
    const int col0 = blockIdx.x * GBN;
    const int tid  = threadIdx.x;

    if (which == 1 && tid < GBM)
        tokens[tid] = x[(row0 + tid) * T_ + t];
    __syncthreads();

    float acc[4][4];
#pragma unroll
    for (int i = 0; i < 4; i++)
#pragma unroll
        for (int j = 0; j < 4; j++) acc[i][j] = 0.f;

    const int ty = tid >> 4, tx = tid & 15;
    const int ar = tid >> 2, ac = (tid & 3) * 4;        // A tile: 64 rows x 16 cols
    const int br = tid >> 4, bc = (tid & 15) * 4;       // B tile: 16 rows x 64 cols

    for (int k0 = 0; k0 < K; k0 += GBK) {
        // load A tile (float4)
        int r = row0 + ar, kc = k0 + ac;
        float4 av;
        if (which == 1) {
            if (kc < 128) av = *reinterpret_cast<const float4*>(&emb_table[tokens[ar] * E_ + kc]);
            else          av = *reinterpret_cast<const float4*>(&g_HH[(size_t)r * 1024 + (kc - 128)]);
        } else {
            av = *reinterpret_cast<const float4*>(&g_HH[(size_t)r * 1024 + kc]);
        }
        As[ac + 0][ar] = av.x; As[ac + 1][ar] = av.y;
        As[ac + 2][ar] = av.z; As[ac + 3][ar] = av.w;

        // load B tile (float4, coalesced)
        float4 bv = *reinterpret_cast<const float4*>(&Bmat[(size_t)(k0 + br) * FOURH + col0 + bc]);
        *reinterpret_cast<float4*>(&Bs[br][bc]) = bv;

        __syncthreads();
#pragma unroll
        for (int kk = 0; kk < GBK; kk++) {
            float4 a = *reinterpret_cast<const float4*>(&As[kk][ty * 4]);
            float4 b = *reinterpret_cast<const float4*>(&Bs[kk][tx * 4]);
            acc[0][0] += a.x * b.x; acc[0][1] += a.x * b.y; acc[0][2] += a.x * b.z; acc[0][3] += a.x * b.w;
            acc[1][0] += a.y * b.x; acc[1][1] += a.y * b.y; acc[1][2] += a.y * b.z; acc[1][3] += a.y * b.w;
            acc[2][0] += a.z * b.x; acc[2][1] += a.z * b.y; acc[2][2] += a.z * b.z; acc[2][3] += a.z * b.w;
            acc[3][0] += a.w * b.x; acc[3][1] += a.w * b.y; acc[3][2] += a.w * b.z; acc[3][3] += a.w * b.w;
        }
        __syncthreads();
    }

    // epilogue: add bias, write G
    float4 bv4 = *reinterpret_cast<const float4*>(&bias[col0 + tx * 4]);
#pragma unroll
    for (int i = 0; i < 4; i++) {
        size_t base = (size_t)(row0 + ty * 4 + i) * FOURH + col0 + tx * 4;
        float4 o;
        o.x = acc[i][0] + bv4.x; o.y = acc[i][1] + bv4.y;
        o.z = acc[i][2] + bv4.z; o.w = acc[i][3] + bv4.w;
        *reinterpret_cast<float4*>(&g_G[base]) = o;
    }
}

// ---------------- LSTM pointwise cell (PyTorch gate order i,f,g,o) ----------------
__global__ void lstm_cell_kernel(int layer) {
    int idx = blockIdx.x * 256 + threadIdx.x;           // 512*512 threads
    int b = idx >> 9, j = idx & 511;
    size_t gb = (size_t)b * FOURH;
    float iv = g_G[gb + j];
    float fv = g_G[gb + 512 + j];
    float gv = g_G[gb + 1024 + j];
    float ov = g_G[gb + 1536 + j];
    float si = 1.f / (1.f + expf(-iv));
    float sf = 1.f / (1.f + expf(-fv));
    float tg = tanhf(gv);
    float so = 1.f / (1.f + expf(-ov));
    float* c = layer ? g_c1 : g_c0;
    float cn = sf * c[idx] + si * tg;
    c[idx] = cn;
    g_HH[(size_t)b * 1024 + (layer ? 512 : 0) + j] = so * tanhf(cn);
}

// ---------------- fc + relu + softmax + NLL ----------------
__global__ void fc_kernel(int t, const int* __restrict__ x,
                          const float* __restrict__ Wfc, const float* __restrict__ bfc,
                          float* __restrict__ out) {
    int b = blockIdx.x;
    __shared__ float h[H_];
    __shared__ float lg[V_];
    __shared__ float red[2];
    int tid = threadIdx.x;                              // 64 threads

    for (int k = tid; k < H_; k += 64)
        h[k] = g_HH[(size_t)b * 1024 + 512 + k];
    __syncthreads();

    if (tid < V_) {
        float s = bfc[tid];
        const float* wr = &Wfc[tid * H_];
#pragma unroll 4
        for (int k = 0; k < H_; k++) s += h[k] * wr[k];
        lg[tid] = fmaxf(s, 0.f);                        // relu BEFORE softmax (as in source)
    }
    __syncthreads();

    if (tid == 0) {
        float m = -1e30f;
        for (int v = 0; v < V_; v++) m = fmaxf(m, lg[v]);
        float sum = 0.f;
        for (int v = 0; v < V_; v++) sum += expf(lg[v] - m);
        red[0] = m; red[1] = sum;
        int tgt = x[b * T_ + t + 1];
        g_loss[b * TSTEPS + t] = (tgt == IGN) ? 0.f : -lg[tgt];   // NLL on relu'd logits
    }
    __syncthreads();

    if (tid < V_)
        out[OFF_PROBS + ((size_t)b * TSTEPS + t) * V_ + tid] = expf(lg[tid] - red[0]) / red[1];
}

// ---------------- sample_loss + mean ----------------
__global__ void finalize_kernel(const int* __restrict__ x, float* __restrict__ out) {
    __shared__ float red[B_];
    int b = threadIdx.x;                                // 512 threads, 1 block
    float s = 0.f;
    for (int t = 0; t < TSTEPS; t++) s += g_loss[b * TSTEPS + t];
    int len = 0;
    for (int t = 0; t < T_; t++) len += (x[b * T_ + t] != IGN);
    float sl = s / (float)len;
    out[OFF_SL + b] = sl;
    red[b] = sl;
    __syncthreads();
    for (int st = 256; st > 0; st >>= 1) {
        if (b < st) red[b] += red[b + st];
        __syncthreads();
    }
    if (b == 0) out[OFF_MEAN] = red[0] / (float)B_;
}

// ---------------- launch ----------------
extern "C" void kernel_launch(void* const* d_in, const int* in_sizes, int n_in,
                              void* d_out, int out_size) {
    const int*   x    = (const int*)  d_in[0];
    const float* tab  = (const float*)d_in[1];
    const float* Wih0 = (const float*)d_in[2];
    const float* Whh0 = (const float*)d_in[3];
    const float* bih0 = (const float*)d_in[4];
    const float* bhh0 = (const float*)d_in[5];
    const float* Wih1 = (const float*)d_in[6];
    const float* Whh1 = (const float*)d_in[7];
    const float* bih1 = (const float*)d_in[8];
    const float* bhh1 = (const float*)d_in[9];
    const float* Wfc  = (const float*)d_in[10];
    const float* bfc  = (const float*)d_in[11];
    float* out = (float*)d_out;

    prep_kernel<<<(1024 * FOURH) / 256, 256>>>(Wih0, Whh0, Wih1, Whh1, bih0, bhh0, bih1, bhh1);
    embed_kernel<<<(int)((EMB_N / 4 + 255) / 256), 256>>>(x, tab, out + OFF_EMB);

    dim3 ggrid(FOURH / GBN, B_ / GBM);                  // (32, 8)
    for (int t = 0; t < TSTEPS; t++) {
        gemm_step_kernel<<<ggrid, 256>>>(1, t, x, tab);
        lstm_cell_kernel<<<(B_ * H_) / 256, 256>>>(0);
        gemm_step_kernel<<<ggrid, 256>>>(2, t, x, tab);
        lstm_cell_kernel<<<(B_ * H_) / 256, 256>>>(1);
        fc_kernel<<<B_, 64>>>(t, x, Wfc, bfc, out);
    }
    finalize_kernel<<<1, B_>>>(x, out);
}

// round 5
// speedup vs baseline: 2.9354x; 2.9354x over previous
#include <cuda_runtime.h>
#include <cuda_bf16.h>
#include <math.h>
#include <stdint.h>

#define B_      512
#define T_      128
#define V_      36
#define E_      128
#define H_      512
#define TSTEPS  127

#define PROBS_N  ((size_t)B_ * TSTEPS * V_)
#define EMB_N    ((size_t)B_ * T_ * E_)
#define OFF_PROBS 0
#define OFF_EMB   (PROBS_N)
#define OFF_SL    (OFF_EMB + EMB_N)
#define OFF_MEAN  (OFF_SL + B_)

// ---------------- device scratch (no allocation) ----------------
// Weights split bf16 hi/lo. Column interleave: out-col c <-> orig gate row
//   r = ((c>>3)&3)*512 + (c>>5)*8 + (c&7)   (gate = (c%32)/8, j = (c/32)*8 + c%8)
__device__ __nv_bfloat16 g_W0h[2048 * 640];
__device__ __nv_bfloat16 g_W0l[2048 * 640];
__device__ __nv_bfloat16 g_W1h[2048 * 1024];
__device__ __nv_bfloat16 g_W1l[2048 * 1024];
__device__ float g_b0i[2048], g_b1i[2048];
__device__ __nv_bfloat16 g_Eh[36 * 128], g_El[36 * 128];
__device__ __nv_bfloat16 g_h0h[2][512 * 512], g_h0l[2][512 * 512];
__device__ __nv_bfloat16 g_h1h[2][512 * 512], g_h1l[2][512 * 512];
__device__ float g_c0[512 * 512], g_c1[512 * 512];
__device__ float g_loss[512 * TSTEPS];

// ---------------- smem layout (bytes) ----------------
// A/B tiles: [128 rows][32 k] bf16, row stride 40 elems (80B) for conflict-free ldmatrix
#define LDA     40
#define S_AHI   0
#define S_ALO   10240
#define S_BHI   20480
#define S_BLO   30720
#define S_TOK   40960
#define SMEM_BYTES 41472

// ---------------- PTX helpers ----------------
__device__ __forceinline__ uint32_t smem_u32(const void* p) {
    uint32_t a;
    asm("{ .reg .u64 t; cvta.to.shared.u64 t, %1; cvt.u32.u64 %0, t; }" : "=r"(a) : "l"(p));
    return a;
}
__device__ __forceinline__ void ldsm_x4(uint32_t& r0, uint32_t& r1, uint32_t& r2, uint32_t& r3,
                                        uint32_t addr) {
    asm volatile("ldmatrix.sync.aligned.m8n8.x4.shared.b16 {%0,%1,%2,%3}, [%4];"
                 : "=r"(r0), "=r"(r1), "=r"(r2), "=r"(r3) : "r"(addr));
}
__device__ __forceinline__ void ldsm_x2(uint32_t& r0, uint32_t& r1, uint32_t addr) {
    asm volatile("ldmatrix.sync.aligned.m8n8.x2.shared.b16 {%0,%1}, [%2];"
                 : "=r"(r0), "=r"(r1) : "r"(addr));
}
__device__ __forceinline__ void mma16816(float* d, const uint32_t* a, const uint32_t* b) {
    asm volatile(
        "mma.sync.aligned.m16n8k16.row.col.f32.bf16.bf16.f32 "
        "{%0,%1,%2,%3}, {%4,%5,%6,%7}, {%8,%9}, {%0,%1,%2,%3};"
        : "+f"(d[0]), "+f"(d[1]), "+f"(d[2]), "+f"(d[3])
        : "r"(a[0]), "r"(a[1]), "r"(a[2]), "r"(a[3]), "r"(b[0]), "r"(b[1]));
}

// ---------------- GEMM + fused LSTM cell ----------------
// which==0: step s: A = [emb(x[:,s]) | h0[par_prev]], K=640,  writes h0[par_cur], c0
// which==1: step s: A = [h0[par_cur] | h1[par_prev]], K=1024, writes h1[par_cur], c1
__device__ void gemm_part(char* sm, int tileid, int which, int s, const int* __restrict__ x) {
    const int tid = threadIdx.x;
    const int m0 = (tileid >> 4) * 128;
    const int col0 = (tileid & 15) * 128;
    const int K = which ? 1024 : 640;
    const int nch = K / 32;
    const int par_cur = s & 1, par_prev = (s + 1) & 1;
    const uint32_t sb = smem_u32(sm);

    int* tok_s = (int*)(sm + S_TOK);
    if (which == 0 && tid < 128) tok_s[tid] = x[(m0 + tid) * T_ + s];
    __syncthreads();

    const __nv_bfloat16* __restrict__ Wh = which ? g_W1h : g_W0h;
    const __nv_bfloat16* __restrict__ Wl = which ? g_W1l : g_W0l;

    const int warp = tid >> 5, lane = tid & 31;
    const int wm = warp >> 2, wn = warp & 3;

    float acc[4][4][4];
#pragma unroll
    for (int i = 0; i < 4; i++)
#pragma unroll
        for (int q = 0; q < 4; q++)
#pragma unroll
            for (int r = 0; r < 4; r++) acc[i][q][r] = 0.f;

    // ldmatrix per-thread base addresses
    const int arow = wm * 64 + (lane & 15);
    const int ahalf = (lane >> 4) * 8;
    const uint32_t a_hi_base = sb + S_AHI + (arow * LDA + ahalf) * 2;
    const uint32_t a_lo_base = sb + S_ALO + (arow * LDA + ahalf) * 2;
    const int brow = wn * 32 + (lane & 7);
    const int bhalf = ((lane >> 3) & 1) * 8;
    const uint32_t b_hi_base = sb + S_BHI + (brow * LDA + bhalf) * 2;
    const uint32_t b_lo_base = sb + S_BLO + (brow * LDA + bhalf) * 2;

    const int ldr = (tid >> 2);          // 0..63 row within half-tile per iter
    const int ldk = (tid & 3) * 8;       // k offset 0/8/16/24

    for (int c = 0; c < nch; c++) {
        const int kb = c * 32;
        // ---- load A/B chunk into smem ----
#pragma unroll
        for (int it = 0; it < 2; it++) {
            const int r = it * 64 + ldr;                 // 0..127
            const int kk = kb + ldk;
            const __nv_bfloat16 *pah, *pal;
            if (which) {
                if (kb < 512) {
                    size_t o = (size_t)(m0 + r) * 512 + kk;
                    pah = &g_h0h[par_cur][o]; pal = &g_h0l[par_cur][o];
                } else {
                    size_t o = (size_t)(m0 + r) * 512 + kk - 512;
                    pah = &g_h1h[par_prev][o]; pal = &g_h1l[par_prev][o];
                }
            } else {
                if (kb < 128) {
                    size_t o = (size_t)tok_s[r] * 128 + kk;
                    pah = &g_Eh[o]; pal = &g_El[o];
                } else {
                    size_t o = (size_t)(m0 + r) * 512 + kk - 128;
                    pah = &g_h0h[par_prev][o]; pal = &g_h0l[par_prev][o];
                }
            }
            const int dst = (r * LDA + ldk) * 2;
            *(uint4*)(sm + S_AHI + dst) = *(const uint4*)pah;
            *(uint4*)(sm + S_ALO + dst) = *(const uint4*)pal;
            size_t bo = (size_t)(col0 + r) * K + kk;
            *(uint4*)(sm + S_BHI + dst) = *(const uint4*)&Wh[bo];
            *(uint4*)(sm + S_BLO + dst) = *(const uint4*)&Wl[bo];
        }
        __syncthreads();

        // ---- compute ----
#pragma unroll
        for (int kk = 0; kk < 2; kk++) {
            const uint32_t koff = (uint32_t)(kk * 16 * 2);
            uint32_t af[4][4], bh[4][2], bl[4][2];
#pragma unroll
            for (int q = 0; q < 4; q++) {
                ldsm_x2(bh[q][0], bh[q][1], b_hi_base + koff + q * (8 * LDA * 2));
                ldsm_x2(bl[q][0], bl[q][1], b_lo_base + koff + q * (8 * LDA * 2));
            }
#pragma unroll
            for (int mf = 0; mf < 4; mf++)
                ldsm_x4(af[mf][0], af[mf][1], af[mf][2], af[mf][3],
                        a_hi_base + koff + mf * (16 * LDA * 2));
#pragma unroll
            for (int mf = 0; mf < 4; mf++)
#pragma unroll
                for (int q = 0; q < 4; q++) {
                    mma16816(acc[mf][q], af[mf], bh[q]);   // hi*hi
                    mma16816(acc[mf][q], af[mf], bl[q]);   // hi*lo
                }
#pragma unroll
            for (int mf = 0; mf < 4; mf++)
                ldsm_x4(af[mf][0], af[mf][1], af[mf][2], af[mf][3],
                        a_lo_base + koff + mf * (16 * LDA * 2));
#pragma unroll
            for (int mf = 0; mf < 4; mf++)
#pragma unroll
                for (int q = 0; q < 4; q++)
                    mma16816(acc[mf][q], af[mf], bh[q]);   // lo*hi
        }
        __syncthreads();
    }

    // ---- fused LSTM cell epilogue ----
    const float* __restrict__ bias = which ? g_b1i : g_b0i;
    float* __restrict__ Cc = which ? g_c1 : g_c0;
    __nv_bfloat16* __restrict__ Hh = which ? g_h1h[par_cur] : g_h0h[par_cur];
    __nv_bfloat16* __restrict__ Hl = which ? g_h1l[par_cur] : g_h0l[par_cur];

    const int p = lane & 3;
    const int rowb = lane >> 2;
    const int jbase = (col0 >> 2) + wn * 8;      // 8 j's per warp n-block
    float bi[4][2];
#pragma unroll
    for (int g = 0; g < 4; g++) {
        bi[g][0] = bias[col0 + wn * 32 + g * 8 + 2 * p + 0];
        bi[g][1] = bias[col0 + wn * 32 + g * 8 + 2 * p + 1];
    }

#pragma unroll
    for (int mf = 0; mf < 4; mf++) {
#pragma unroll
        for (int r2 = 0; r2 < 2; r2++) {
            const int m = m0 + wm * 64 + mf * 16 + rowb + r2 * 8;
            const size_t cb = (size_t)m * 512 + jbase + 2 * p;
            float2 cold = *(const float2*)&Cc[cb];
            float hn[2], cn[2];
#pragma unroll
            for (int bit = 0; bit < 2; bit++) {
                const int ri = r2 * 2 + bit;
                float iv = acc[mf][0][ri] + bi[0][bit];
                float fv = acc[mf][1][ri] + bi[1][bit];
                float gv = acc[mf][2][ri] + bi[2][bit];
                float ov = acc[mf][3][ri] + bi[3][bit];
                float si = 1.f / (1.f + expf(-iv));
                float sf = 1.f / (1.f + expf(-fv));
                float tg = tanhf(gv);
                float so = 1.f / (1.f + expf(-ov));
                float co = bit ? cold.y : cold.x;
                cn[bit] = sf * co + si * tg;
                hn[bit] = so * tanhf(cn[bit]);
            }
            *(float2*)&Cc[cb] = make_float2(cn[0], cn[1]);
            __nv_bfloat16 h0b = __float2bfloat16(hn[0]);
            __nv_bfloat16 h1b = __float2bfloat16(hn[1]);
            __nv_bfloat16 l0b = __float2bfloat16(hn[0] - __bfloat162float(h0b));
            __nv_bfloat16 l1b = __float2bfloat16(hn[1] - __bfloat162float(h1b));
            uint32_t hp = (uint32_t)__bfloat16_as_ushort(h0b) |
                          ((uint32_t)__bfloat16_as_ushort(h1b) << 16);
            uint32_t lp = (uint32_t)__bfloat16_as_ushort(l0b) |
                          ((uint32_t)__bfloat16_as_ushort(l1b) << 16);
            *(uint32_t*)&Hh[cb] = hp;
            *(uint32_t*)&Hl[cb] = lp;
        }
    }
}

// ---------------- fc + relu + softmax + NLL (warp-per-batch, 256 thr) ----------------
__device__ void fc_part(char* sm, int fid, int s, const int* __restrict__ x,
                        const float* __restrict__ Wfc, const float* __restrict__ bfc,
                        float* __restrict__ out) {
    const int tid = threadIdx.x;
    float* hs = (float*)sm;               // [8][512]
    float* lgs = (float*)(sm + 16384);    // [8][40]
    const int b0 = fid * 8;
    const int par = s & 1;
    for (int i = tid; i < 8 * 512; i += 256) {
        int b = i >> 9, k = i & 511;
        size_t idx = (size_t)(b0 + b) * 512 + k;
        hs[i] = __bfloat162float(g_h1h[par][idx]) + __bfloat162float(g_h1l[par][idx]);
    }
    __syncthreads();
    const int w = tid >> 5, lane = tid & 31;
    const int b = b0 + w;
    const float* hb = hs + w * 512;
    for (int v = 0; v < V_; v++) {
        float sum = 0.f;
#pragma unroll
        for (int kk = 0; kk < 16; kk++) {
            int k = lane + kk * 32;
            sum += hb[k] * Wfc[v * 512 + k];
        }
#pragma unroll
        for (int o = 16; o; o >>= 1) sum += __shfl_xor_sync(0xffffffffu, sum, o);
        if (lane == 0) lgs[w * 40 + v] = fmaxf(sum + bfc[v], 0.f);
    }
    __syncwarp();
    if (lane == 0) {
        float mx = -1e30f;
        for (int v = 0; v < V_; v++) mx = fmaxf(mx, lgs[w * 40 + v]);
        float se = 0.f;
        for (int v = 0; v < V_; v++) se += expf(lgs[w * 40 + v] - mx);
        lgs[w * 40 + 36] = mx;
        lgs[w * 40 + 37] = se;
        int tgt = x[b * T_ + s + 1];
        g_loss[b * TSTEPS + s] = (tgt == 0) ? 0.f : -lgs[w * 40 + tgt];
    }
    __syncwarp();
    for (int v = lane; v < V_; v += 32) {
        float pr = expf(lgs[w * 40 + v] - lgs[w * 40 + 36]) / lgs[w * 40 + 37];
        out[OFF_PROBS + ((size_t)b * TSTEPS + s) * V_ + v] = pr;
    }
}

// ---------------- step kernel ----------------
// mode 0: gemm0(step 0), grid 64
// mode 1: gemm1(t) [0..63] + gemm0(t+1) [64..127, skip t==126] + fc(t-1) [128..191, skip t==0]
// mode 2: fc(126), grid 64
__global__ __launch_bounds__(256, 2) void step_kernel(int t, int mode,
        const int* __restrict__ x, const float* __restrict__ Wfc,
        const float* __restrict__ bfc, float* __restrict__ out) {
    extern __shared__ char sm[];
    int bid = blockIdx.x;
    if (mode == 0) { gemm_part(sm, bid, 0, 0, x); return; }
    if (mode == 2) { fc_part(sm, bid, 126, x, Wfc, bfc, out); return; }
    if (bid < 64) {
        gemm_part(sm, bid, 1, t, x);
    } else if (bid < 128) {
        if (t < 126) gemm_part(sm, bid - 64, 0, t + 1, x);
    } else {
        if (t > 0) fc_part(sm, bid - 128, t - 1, x, Wfc, bfc, out);
    }
}

// ---------------- prologue ----------------
__global__ void prep_kernel(const float* __restrict__ Wih0, const float* __restrict__ Whh0,
                            const float* __restrict__ Wih1, const float* __restrict__ Whh1,
                            const float* __restrict__ bi0, const float* __restrict__ bh0,
                            const float* __restrict__ bi1, const float* __restrict__ bh1,
                            const float* __restrict__ tab) {
    int i = blockIdx.x * 256 + threadIdx.x;
    if (i < 2048 * 1024) {
        int np = i >> 10, k = i & 1023;
        int r = ((np >> 3) & 3) * 512 + (np >> 5) * 8 + (np & 7);
        float v = (k < 512) ? Wih1[r * 512 + k] : Whh1[r * 512 + k - 512];
        __nv_bfloat16 hi = __float2bfloat16(v);
        g_W1h[i] = hi;
        g_W1l[i] = __float2bfloat16(v - __bfloat162float(hi));
    }
    if (i < 2048 * 640) {
        int np = i / 640, k = i - np * 640;
        int r = ((np >> 3) & 3) * 512 + (np >> 5) * 8 + (np & 7);
        float v = (k < 128) ? Wih0[r * 128 + k] : Whh0[r * 512 + k - 128];
        __nv_bfloat16 hi = __float2bfloat16(v);
        g_W0h[i] = hi;
        g_W0l[i] = __float2bfloat16(v - __bfloat162float(hi));
    }
    if (i < 36 * 128) {
        float v = tab[i];
        __nv_bfloat16 hi = __float2bfloat16(v);
        g_Eh[i] = hi;
        g_El[i] = __float2bfloat16(v - __bfloat162float(hi));
    }
    if (i < 2048) {
        int r = ((i >> 3) & 3) * 512 + (i >> 5) * 8 + (i & 7);
        g_b0i[i] = bi0[r] + bh0[r];
        g_b1i[i] = bi1[r] + bh1[r];
    }
    if (i < 512 * 512) {
        g_c0[i] = 0.f; g_c1[i] = 0.f;
        __nv_bfloat16 z = __float2bfloat16(0.f);
        g_h0h[1][i] = z; g_h0l[1][i] = z;
        g_h1h[1][i] = z; g_h1l[1][i] = z;
    }
}

// ---------------- embedding output ----------------
__global__ void embed_kernel(const int* __restrict__ x, const float* __restrict__ tab,
                             float* __restrict__ out_emb) {
    int idx = blockIdx.x * 256 + threadIdx.x;
    if (idx >= (int)(EMB_N / 4)) return;
    int e4 = idx & 31;
    int bt = idx >> 5;
    int tok = x[bt];
    float4 v = reinterpret_cast<const float4*>(tab)[tok * 32 + e4];
    reinterpret_cast<float4*>(out_emb)[idx] = v;
}

// ---------------- finalize ----------------
__global__ void finalize_kernel(const int* __restrict__ x, float* __restrict__ out) {
    __shared__ float red[B_];
    int b = threadIdx.x;
    float s = 0.f;
    for (int t = 0; t < TSTEPS; t++) s += g_loss[b * TSTEPS + t];
    int len = 0;
    for (int t = 0; t < T_; t++) len += (x[b * T_ + t] != 0);
    float sl = s / (float)len;
    out[OFF_SL + b] = sl;
    red[b] = sl;
    __syncthreads();
    for (int st = 256; st > 0; st >>= 1) {
        if (b < st) red[b] += red[b + st];
        __syncthreads();
    }
    if (b == 0) out[OFF_MEAN] = red[0] / (float)B_;
}

// ---------------- launch ----------------
extern "C" void kernel_launch(void* const* d_in, const int* in_sizes, int n_in,
                              void* d_out, int out_size) {
    const int*   x    = (const int*)  d_in[0];
    const float* tab  = (const float*)d_in[1];
    const float* Wih0 = (const float*)d_in[2];
    const float* Whh0 = (const float*)d_in[3];
    const float* bih0 = (const float*)d_in[4];
    const float* bhh0 = (const float*)d_in[5];
    const float* bih1 = (const float*)d_in[8];
    const float* Wih1 = (const float*)d_in[6];
    const float* Whh1 = (const float*)d_in[7];
    const float* bhh1 = (const float*)d_in[9];
    const float* Wfc  = (const float*)d_in[10];
    const float* bfc  = (const float*)d_in[11];
    float* out = (float*)d_out;

    prep_kernel<<<(2048 * 1024) / 256, 256>>>(Wih0, Whh0, Wih1, Whh1,
                                              bih0, bhh0, bih1, bhh1, tab);
    embed_kernel<<<(int)((EMB_N / 4 + 255) / 256), 256>>>(x, tab, out + OFF_EMB);

    step_kernel<<<64, 256, SMEM_BYTES>>>(0, 0, x, Wfc, bfc, out);
    for (int t = 0; t < TSTEPS; t++)
        step_kernel<<<192, 256, SMEM_BYTES>>>(t, 1, x, Wfc, bfc, out);
    step_kernel<<<64, 256, SMEM_BYTES>>>(0, 2, x, Wfc, bfc, out);
    finalize_kernel<<<1, B_>>>(x, out);
}

// round 6
// speedup vs baseline: 3.4758x; 1.1841x over previous
#include <cuda_runtime.h>
#include <cuda_bf16.h>
#include <math.h>
#include <stdint.h>

#define B_      512
#define T_      128
#define V_      36
#define E_      128
#define H_      512
#define TSTEPS  127

#define PROBS_N  ((size_t)B_ * TSTEPS * V_)
#define EMB_N    ((size_t)B_ * T_ * E_)
#define OFF_PROBS 0
#define OFF_EMB   (PROBS_N)
#define OFF_SL    (OFF_EMB + EMB_N)
#define OFF_MEAN  (OFF_SL + B_)

// ---------------- device scratch (no allocation) ----------------
// Weights split bf16 hi/lo. Column interleave: out-col c <-> orig gate row
//   r = ((c>>3)&3)*512 + (c>>5)*8 + (c&7)
__device__ __nv_bfloat16 g_W0h[2048 * 640];
__device__ __nv_bfloat16 g_W0l[2048 * 640];
__device__ __nv_bfloat16 g_W1h[2048 * 1024];
__device__ __nv_bfloat16 g_W1l[2048 * 1024];
__device__ float g_b0i[2048], g_b1i[2048];
__device__ __nv_bfloat16 g_Eh[36 * 128], g_El[36 * 128];
__device__ __nv_bfloat16 g_h0h[2][512 * 512], g_h0l[2][512 * 512];
__device__ __nv_bfloat16 g_h1h[2][512 * 512], g_h1l[2][512 * 512];
__device__ float g_c0[512 * 512], g_c1[512 * 512];
__device__ float g_loss[512 * TSTEPS];

// ---------------- smem layout (bytes) ----------------
// Per stage: A hi/lo + B hi/lo tiles, each [128 rows][32 k] bf16, row stride 40
#define LDA      40
#define TILE_B   10240
#define S_AHI    0
#define S_ALO    10240
#define S_BHI    20480
#define S_BLO    30720
#define STAGE_B  40960
#define NSTAGE   3
#define S_TOK    (NSTAGE * STAGE_B)          // 122880
#define SMEM_BYTES (S_TOK + 512)             // 123392

// ---------------- PTX helpers ----------------
__device__ __forceinline__ uint32_t smem_u32(const void* p) {
    uint32_t a;
    asm("{ .reg .u64 t; cvta.to.shared.u64 t, %1; cvt.u32.u64 %0, t; }" : "=r"(a) : "l"(p));
    return a;
}
__device__ __forceinline__ void cp16(uint32_t dst, const void* src) {
    asm volatile("cp.async.cg.shared.global [%0], [%1], 16;" :: "r"(dst), "l"(src));
}
__device__ __forceinline__ void cp_commit() { asm volatile("cp.async.commit_group;" ::: "memory"); }
__device__ __forceinline__ void cp_wait0()  { asm volatile("cp.async.wait_group 0;" ::: "memory"); }
__device__ __forceinline__ void cp_wait1()  { asm volatile("cp.async.wait_group 1;" ::: "memory"); }
__device__ __forceinline__ void ldsm_x4(uint32_t& r0, uint32_t& r1, uint32_t& r2, uint32_t& r3,
                                        uint32_t addr) {
    asm volatile("ldmatrix.sync.aligned.m8n8.x4.shared.b16 {%0,%1,%2,%3}, [%4];"
                 : "=r"(r0), "=r"(r1), "=r"(r2), "=r"(r3) : "r"(addr));
}
__device__ __forceinline__ void ldsm_x2(uint32_t& r0, uint32_t& r1, uint32_t addr) {
    asm volatile("ldmatrix.sync.aligned.m8n8.x2.shared.b16 {%0,%1}, [%2];"
                 : "=r"(r0), "=r"(r1) : "r"(addr));
}
__device__ __forceinline__ void mma16816(float* d, const uint32_t* a, const uint32_t* b) {
    asm volatile(
        "mma.sync.aligned.m16n8k16.row.col.f32.bf16.bf16.f32 "
        "{%0,%1,%2,%3}, {%4,%5,%6,%7}, {%8,%9}, {%0,%1,%2,%3};"
        : "+f"(d[0]), "+f"(d[1]), "+f"(d[2]), "+f"(d[3])
        : "r"(a[0]), "r"(a[1]), "r"(a[2]), "r"(a[3]), "r"(b[0]), "r"(b[1]));
}

// ---------------- GEMM + fused LSTM cell ----------------
// which==0: step s: A = [emb(x[:,s]) | h0[par_prev]], K=640,  writes h0[par_cur], c0
// which==1: step s: A = [h0[par_cur] | h1[par_prev]], K=1024, writes h1[par_cur], c1
__device__ void gemm_part(char* sm, int tileid, int which, int s, const int* __restrict__ x) {
    const int tid = threadIdx.x;
    const int m0 = (tileid >> 4) * 128;
    const int col0 = (tileid & 15) * 128;
    const int K = which ? 1024 : 640;
    const int nch = K / 32;
    const int par_cur = s & 1, par_prev = (s + 1) & 1;
    const uint32_t sb = smem_u32(sm);

    int* tok_s = (int*)(sm + S_TOK);
    if (which == 0 && tid < 128) tok_s[tid] = x[(m0 + tid) * T_ + s];
    __syncthreads();

    const __nv_bfloat16* __restrict__ Wh = which ? g_W1h : g_W0h;
    const __nv_bfloat16* __restrict__ Wl = which ? g_W1l : g_W0l;

    const int warp = tid >> 5, lane = tid & 31;
    const int wm = warp >> 2, wn = warp & 3;

    const int ldr = (tid >> 2);          // 0..63
    const int ldk = (tid & 3) * 8;       // 0/8/16/24

    // async-load one 32-k chunk into stage buf
    auto load_chunk = [&](int c, int buf) {
        const int kb = c * 32;
        const uint32_t sbst = sb + buf * STAGE_B;
#pragma unroll
        for (int it = 0; it < 2; it++) {
            const int r = it * 64 + ldr;
            const int kk = kb + ldk;
            const __nv_bfloat16 *pah, *pal;
            if (which) {
                if (kb < 512) {
                    size_t o = (size_t)(m0 + r) * 512 + kk;
                    pah = &g_h0h[par_cur][o]; pal = &g_h0l[par_cur][o];
                } else {
                    size_t o = (size_t)(m0 + r) * 512 + kk - 512;
                    pah = &g_h1h[par_prev][o]; pal = &g_h1l[par_prev][o];
                }
            } else {
                if (kb < 128) {
                    size_t o = (size_t)tok_s[r] * 128 + kk;
                    pah = &g_Eh[o]; pal = &g_El[o];
                } else {
                    size_t o = (size_t)(m0 + r) * 512 + kk - 128;
                    pah = &g_h0h[par_prev][o]; pal = &g_h0l[par_prev][o];
                }
            }
            const int dst = (r * LDA + ldk) * 2;
            cp16(sbst + S_AHI + dst, pah);
            cp16(sbst + S_ALO + dst, pal);
            size_t bo = (size_t)(col0 + r) * K + kk;
            cp16(sbst + S_BHI + dst, &Wh[bo]);
            cp16(sbst + S_BLO + dst, &Wl[bo]);
        }
    };

    float acc[4][4][4];
#pragma unroll
    for (int i = 0; i < 4; i++)
#pragma unroll
        for (int q = 0; q < 4; q++)
#pragma unroll
            for (int r = 0; r < 4; r++) acc[i][q][r] = 0.f;

    // ldmatrix per-thread base addresses (stage 0)
    const int arow = wm * 64 + (lane & 15);
    const int ahalf = (lane >> 4) * 8;
    const uint32_t a_hi0 = sb + S_AHI + (arow * LDA + ahalf) * 2;
    const uint32_t a_lo0 = sb + S_ALO + (arow * LDA + ahalf) * 2;
    const int brow = wn * 32 + (lane & 7);
    const int bhalf = ((lane >> 3) & 1) * 8;
    const uint32_t b_hi0 = sb + S_BHI + (brow * LDA + bhalf) * 2;
    const uint32_t b_lo0 = sb + S_BLO + (brow * LDA + bhalf) * 2;

    // prologue: 2 chunks in flight
    load_chunk(0, 0); cp_commit();
    load_chunk(1, 1); cp_commit();

    int buf = 0;
    for (int c = 0; c < nch; c++) {
        if (c == nch - 1) cp_wait0(); else cp_wait1();
        __syncthreads();
        if (c + 2 < nch) {
            int nb = buf + 2; if (nb >= NSTAGE) nb -= NSTAGE;
            load_chunk(c + 2, nb);
            cp_commit();
        }
        const uint32_t so = (uint32_t)(buf * STAGE_B);
#pragma unroll
        for (int kk = 0; kk < 2; kk++) {
            const uint32_t koff = so + (uint32_t)(kk * 16 * 2);
            uint32_t af[4][4], bh[4][2], bl[4][2];
#pragma unroll
            for (int q = 0; q < 4; q++) {
                ldsm_x2(bh[q][0], bh[q][1], b_hi0 + koff + q * (8 * LDA * 2));
                ldsm_x2(bl[q][0], bl[q][1], b_lo0 + koff + q * (8 * LDA * 2));
            }
#pragma unroll
            for (int mf = 0; mf < 4; mf++)
                ldsm_x4(af[mf][0], af[mf][1], af[mf][2], af[mf][3],
                        a_hi0 + koff + mf * (16 * LDA * 2));
#pragma unroll
            for (int mf = 0; mf < 4; mf++)
#pragma unroll
                for (int q = 0; q < 4; q++) {
                    mma16816(acc[mf][q], af[mf], bh[q]);   // hi*hi
                    mma16816(acc[mf][q], af[mf], bl[q]);   // hi*lo
                }
#pragma unroll
            for (int mf = 0; mf < 4; mf++)
                ldsm_x4(af[mf][0], af[mf][1], af[mf][2], af[mf][3],
                        a_lo0 + koff + mf * (16 * LDA * 2));
#pragma unroll
            for (int mf = 0; mf < 4; mf++)
#pragma unroll
                for (int q = 0; q < 4; q++)
                    mma16816(acc[mf][q], af[mf], bh[q]);   // lo*hi
        }
        if (++buf == NSTAGE) buf = 0;
    }

    // ---- fused LSTM cell epilogue ----
    const float* __restrict__ bias = which ? g_b1i : g_b0i;
    float* __restrict__ Cc = which ? g_c1 : g_c0;
    __nv_bfloat16* __restrict__ Hh = which ? g_h1h[par_cur] : g_h0h[par_cur];
    __nv_bfloat16* __restrict__ Hl = which ? g_h1l[par_cur] : g_h0l[par_cur];

    const int p = lane & 3;
    const int rowb = lane >> 2;
    const int jbase = (col0 >> 2) + wn * 8;
    float bi[4][2];
#pragma unroll
    for (int g = 0; g < 4; g++) {
        bi[g][0] = bias[col0 + wn * 32 + g * 8 + 2 * p + 0];
        bi[g][1] = bias[col0 + wn * 32 + g * 8 + 2 * p + 1];
    }

#pragma unroll
    for (int mf = 0; mf < 4; mf++) {
#pragma unroll
        for (int r2 = 0; r2 < 2; r2++) {
            const int m = m0 + wm * 64 + mf * 16 + rowb + r2 * 8;
            const size_t cb = (size_t)m * 512 + jbase + 2 * p;
            float2 cold = *(const float2*)&Cc[cb];
            float hn[2], cn[2];
#pragma unroll
            for (int bit = 0; bit < 2; bit++) {
                const int ri = r2 * 2 + bit;
                float iv = acc[mf][0][ri] + bi[0][bit];
                float fv = acc[mf][1][ri] + bi[1][bit];
                float gv = acc[mf][2][ri] + bi[2][bit];
                float ov = acc[mf][3][ri] + bi[3][bit];
                float si = 1.f / (1.f + expf(-iv));
                float sf = 1.f / (1.f + expf(-fv));
                float tg = tanhf(gv);
                float so = 1.f / (1.f + expf(-ov));
                float co = bit ? cold.y : cold.x;
                cn[bit] = sf * co + si * tg;
                hn[bit] = so * tanhf(cn[bit]);
            }
            *(float2*)&Cc[cb] = make_float2(cn[0], cn[1]);
            __nv_bfloat16 h0b = __float2bfloat16(hn[0]);
            __nv_bfloat16 h1b = __float2bfloat16(hn[1]);
            __nv_bfloat16 l0b = __float2bfloat16(hn[0] - __bfloat162float(h0b));
            __nv_bfloat16 l1b = __float2bfloat16(hn[1] - __bfloat162float(h1b));
            uint32_t hp = (uint32_t)__bfloat16_as_ushort(h0b) |
                          ((uint32_t)__bfloat16_as_ushort(h1b) << 16);
            uint32_t lp = (uint32_t)__bfloat16_as_ushort(l0b) |
                          ((uint32_t)__bfloat16_as_ushort(l1b) << 16);
            *(uint32_t*)&Hh[cb] = hp;
            *(uint32_t*)&Hl[cb] = lp;
        }
    }
}

// ---------------- fc + relu + softmax + NLL (32 batches/block, 4/warp) ----------------
__device__ void fc_part(char* sm, int fid, int s, const int* __restrict__ x,
                        const float* __restrict__ Wfc, const float* __restrict__ bfc,
                        float* __restrict__ out) {
    const int tid = threadIdx.x;
    float* hs = (float*)sm;               // [32][512]
    float* lgs = (float*)(sm + 65536);    // [32][40]
    const int b0 = fid * 32;
    const int par = s & 1;
    for (int i = tid; i < 32 * 512; i += 256) {
        int b = i >> 9, k = i & 511;
        size_t idx = (size_t)(b0 + b) * 512 + k;
        hs[i] = __bfloat162float(g_h1h[par][idx]) + __bfloat162float(g_h1l[par][idx]);
    }
    __syncthreads();
    const int w = tid >> 5, lane = tid & 31;
    for (int rep = 0; rep < 4; rep++) {
        const int bl = w * 4 + rep;
        const int b = b0 + bl;
        const float* hb = hs + bl * 512;
        for (int v = 0; v < V_; v++) {
            float sum = 0.f;
#pragma unroll
            for (int kk = 0; kk < 16; kk++) {
                int k = lane + kk * 32;
                sum += hb[k] * Wfc[v * 512 + k];
            }
#pragma unroll
            for (int o = 16; o; o >>= 1) sum += __shfl_xor_sync(0xffffffffu, sum, o);
            if (lane == 0) lgs[bl * 40 + v] = fmaxf(sum + bfc[v], 0.f);
        }
        __syncwarp();
        if (lane == 0) {
            float mx = -1e30f;
            for (int v = 0; v < V_; v++) mx = fmaxf(mx, lgs[bl * 40 + v]);
            float se = 0.f;
            for (int v = 0; v < V_; v++) se += expf(lgs[bl * 40 + v] - mx);
            lgs[bl * 40 + 36] = mx;
            lgs[bl * 40 + 37] = se;
            int tgt = x[b * T_ + s + 1];
            g_loss[b * TSTEPS + s] = (tgt == 0) ? 0.f : -lgs[bl * 40 + tgt];
        }
        __syncwarp();
        for (int v = lane; v < V_; v += 32) {
            float pr = expf(lgs[bl * 40 + v] - lgs[bl * 40 + 36]) / lgs[bl * 40 + 37];
            out[OFF_PROBS + ((size_t)b * TSTEPS + s) * V_ + v] = pr;
        }
        __syncwarp();
    }
}

// ---------------- step kernel ----------------
// mode 0: gemm0(step 0), grid 64
// mode 1: grid 144 = gemm1(t)[0..63] + gemm0(t+1)[64..127, skip t==126] + fc(t-1)[128..143, skip t==0]
// mode 2: fc(126), grid 16
__global__ __launch_bounds__(256, 1) void step_kernel(int t, int mode,
        const int* __restrict__ x, const float* __restrict__ Wfc,
        const float* __restrict__ bfc, float* __restrict__ out) {
    extern __shared__ char sm[];
    int bid = blockIdx.x;
    if (mode == 0) { gemm_part(sm, bid, 0, 0, x); return; }
    if (mode == 2) { fc_part(sm, bid, 126, x, Wfc, bfc, out); return; }
    if (bid < 64) {
        gemm_part(sm, bid, 1, t, x);
    } else if (bid < 128) {
        if (t < 126) gemm_part(sm, bid - 64, 0, t + 1, x);
    } else {
        if (t > 0) fc_part(sm, bid - 128, t - 1, x, Wfc, bfc, out);
    }
}

// ---------------- prologue ----------------
__global__ void prep_kernel(const float* __restrict__ Wih0, const float* __restrict__ Whh0,
                            const float* __restrict__ Wih1, const float* __restrict__ Whh1,
                            const float* __restrict__ bi0, const float* __restrict__ bh0,
                            const float* __restrict__ bi1, const float* __restrict__ bh1,
                            const float* __restrict__ tab) {
    int i = blockIdx.x * 256 + threadIdx.x;
    if (i < 2048 * 1024) {
        int np = i >> 10, k = i & 1023;
        int r = ((np >> 3) & 3) * 512 + (np >> 5) * 8 + (np & 7);
        float v = (k < 512) ? Wih1[r * 512 + k] : Whh1[r * 512 + k - 512];
        __nv_bfloat16 hi = __float2bfloat16(v);
        g_W1h[i] = hi;
        g_W1l[i] = __float2bfloat16(v - __bfloat162float(hi));
    }
    if (i < 2048 * 640) {
        int np = i / 640, k = i - np * 640;
        int r = ((np >> 3) & 3) * 512 + (np >> 5) * 8 + (np & 7);
        float v = (k < 128) ? Wih0[r * 128 + k] : Whh0[r * 512 + k - 128];
        __nv_bfloat16 hi = __float2bfloat16(v);
        g_W0h[i] = hi;
        g_W0l[i] = __float2bfloat16(v - __bfloat162float(hi));
    }
    if (i < 36 * 128) {
        float v = tab[i];
        __nv_bfloat16 hi = __float2bfloat16(v);
        g_Eh[i] = hi;
        g_El[i] = __float2bfloat16(v - __bfloat162float(hi));
    }
    if (i < 2048) {
        int r = ((i >> 3) & 3) * 512 + (i >> 5) * 8 + (i & 7);
        g_b0i[i] = bi0[r] + bh0[r];
        g_b1i[i] = bi1[r] + bh1[r];
    }
    if (i < 512 * 512) {
        g_c0[i] = 0.f; g_c1[i] = 0.f;
        __nv_bfloat16 z = __float2bfloat16(0.f);
        g_h0h[1][i] = z; g_h0l[1][i] = z;
        g_h1h[1][i] = z; g_h1l[1][i] = z;
    }
}

// ---------------- embedding output ----------------
__global__ void embed_kernel(const int* __restrict__ x, const float* __restrict__ tab,
                             float* __restrict__ out_emb) {
    int idx = blockIdx.x * 256 + threadIdx.x;
    if (idx >= (int)(EMB_N / 4)) return;
    int e4 = idx & 31;
    int bt = idx >> 5;
    int tok = x[bt];
    float4 v = reinterpret_cast<const float4*>(tab)[tok * 32 + e4];
    reinterpret_cast<float4*>(out_emb)[idx] = v;
}

// ---------------- finalize ----------------
__global__ void finalize_kernel(const int* __restrict__ x, float* __restrict__ out) {
    __shared__ float red[B_];
    int b = threadIdx.x;
    float s = 0.f;
    for (int t = 0; t < TSTEPS; t++) s += g_loss[b * TSTEPS + t];
    int len = 0;
    for (int t = 0; t < T_; t++) len += (x[b * T_ + t] != 0);
    float sl = s / (float)len;
    out[OFF_SL + b] = sl;
    red[b] = sl;
    __syncthreads();
    for (int st = 256; st > 0; st >>= 1) {
        if (b < st) red[b] += red[b + st];
        __syncthreads();
    }
    if (b == 0) out[OFF_MEAN] = red[0] / (float)B_;
}

// ---------------- launch ----------------
extern "C" void kernel_launch(void* const* d_in, const int* in_sizes, int n_in,
                              void* d_out, int out_size) {
    const int*   x    = (const int*)  d_in[0];
    const float* tab  = (const float*)d_in[1];
    const float* Wih0 = (const float*)d_in[2];
    const float* Whh0 = (const float*)d_in[3];
    const float* bih0 = (const float*)d_in[4];
    const float* bhh0 = (const float*)d_in[5];
    const float* Wih1 = (const float*)d_in[6];
    const float* Whh1 = (const float*)d_in[7];
    const float* bih1 = (const float*)d_in[8];
    const float* bhh1 = (const float*)d_in[9];
    const float* Wfc  = (const float*)d_in[10];
    const float* bfc  = (const float*)d_in[11];
    float* out = (float*)d_out;

    cudaFuncSetAttribute(step_kernel, cudaFuncAttributeMaxDynamicSharedMemorySize, SMEM_BYTES);

    prep_kernel<<<(2048 * 1024) / 256, 256>>>(Wih0, Whh0, Wih1, Whh1,
                                              bih0, bhh0, bih1, bhh1, tab);
    embed_kernel<<<(int)((EMB_N / 4 + 255) / 256), 256>>>(x, tab, out + OFF_EMB);

    step_kernel<<<64, 256, SMEM_BYTES>>>(0, 0, x, Wfc, bfc, out);
    for (int t = 0; t < TSTEPS; t++)
        step_kernel<<<144, 256, SMEM_BYTES>>>(t, 1, x, Wfc, bfc, out);
    step_kernel<<<16, 256, SMEM_BYTES>>>(0, 2, x, Wfc, bfc, out);
    finalize_kernel<<<1, B_>>>(x, out);
}

// round 7
// speedup vs baseline: 3.5675x; 1.0264x over previous
#include <cuda_runtime.h>
#include <cuda_bf16.h>
#include <math.h>
#include <stdint.h>

#define B_      512
#define T_      128
#define V_      36
#define E_      128
#define H_      512
#define TSTEPS  127

#define PROBS_N  ((size_t)B_ * TSTEPS * V_)
#define EMB_N    ((size_t)B_ * T_ * E_)
#define OFF_PROBS 0
#define OFF_EMB   (PROBS_N)
#define OFF_SL    (OFF_EMB + EMB_N)
#define OFF_MEAN  (OFF_SL + B_)

// ---------------- device scratch (no allocation) ----------------
// Weights split bf16 hi/lo. Column interleave: out-col c <-> orig gate row
//   r = ((c>>3)&3)*512 + (c>>5)*8 + (c&7)
__device__ __nv_bfloat16 g_W0h[2048 * 640];
__device__ __nv_bfloat16 g_W0l[2048 * 640];
__device__ __nv_bfloat16 g_W1h[2048 * 1024];
__device__ __nv_bfloat16 g_W1l[2048 * 1024];
__device__ float g_b0i[2048], g_b1i[2048];
__device__ __nv_bfloat16 g_Eh[36 * 128], g_El[36 * 128];
__device__ __nv_bfloat16 g_h0h[2][512 * 512], g_h0l[2][512 * 512];
__device__ __nv_bfloat16 g_h1h[2][512 * 512], g_h1l[2][512 * 512];
__device__ float g_c0[512 * 512], g_c1[512 * 512];
__device__ float g_loss[512 * TSTEPS];

// ---------------- smem layout (bytes) ----------------
#define LDA      40
#define S_AHI    0
#define S_ALO    10240
#define S_BHI    20480
#define S_BLO    30720
#define STAGE_B  40960
#define NSTAGE   3
#define S_TOK    (NSTAGE * STAGE_B)          // 122880
#define SMEM_BYTES (S_TOK + 512)             // 123392

// ---------------- PTX helpers ----------------
__device__ __forceinline__ uint32_t smem_u32(const void* p) {
    uint32_t a;
    asm("{ .reg .u64 t; cvta.to.shared.u64 t, %1; cvt.u32.u64 %0, t; }" : "=r"(a) : "l"(p));
    return a;
}
__device__ __forceinline__ void cp16(uint32_t dst, const void* src) {
    asm volatile("cp.async.cg.shared.global [%0], [%1], 16;" :: "r"(dst), "l"(src));
}
__device__ __forceinline__ void cp_commit() { asm volatile("cp.async.commit_group;" ::: "memory"); }
__device__ __forceinline__ void cp_wait0()  { asm volatile("cp.async.wait_group 0;" ::: "memory"); }
__device__ __forceinline__ void cp_wait1()  { asm volatile("cp.async.wait_group 1;" ::: "memory"); }
__device__ __forceinline__ void ldsm_x4(uint32_t& r0, uint32_t& r1, uint32_t& r2, uint32_t& r3,
                                        uint32_t addr) {
    asm volatile("ldmatrix.sync.aligned.m8n8.x4.shared.b16 {%0,%1,%2,%3}, [%4];"
                 : "=r"(r0), "=r"(r1), "=r"(r2), "=r"(r3) : "r"(addr));
}
__device__ __forceinline__ void ldsm_x2(uint32_t& r0, uint32_t& r1, uint32_t addr) {
    asm volatile("ldmatrix.sync.aligned.m8n8.x2.shared.b16 {%0,%1}, [%2];"
                 : "=r"(r0), "=r"(r1) : "r"(addr));
}
__device__ __forceinline__ void mma16816(float* d, const uint32_t* a, const uint32_t* b) {
    asm volatile(
        "mma.sync.aligned.m16n8k16.row.col.f32.bf16.bf16.f32 "
        "{%0,%1,%2,%3}, {%4,%5,%6,%7}, {%8,%9}, {%0,%1,%2,%3};"
        : "+f"(d[0]), "+f"(d[1]), "+f"(d[2]), "+f"(d[3])
        : "r"(a[0]), "r"(a[1]), "r"(a[2]), "r"(a[3]), "r"(b[0]), "r"(b[1]));
}

// ---------------- GEMM + fused LSTM cell (512 thr, 16 warps 4x4, warp tile 32x32) ----
// which==0: step s: A = [emb(x[:,s]) | h0[par_prev]], K=640,  writes h0[par_cur], c0
// which==1: step s: A = [h0[par_cur] | h1[par_prev]], K=1024, writes h1[par_cur], c1
__device__ void gemm_part(char* sm, int tileid, int which, int s, const int* __restrict__ x) {
    const int tid = threadIdx.x;
    const int m0 = (tileid >> 4) * 128;
    const int col0 = (tileid & 15) * 128;
    const int K = which ? 1024 : 640;
    const int nch = K / 32;
    const int par_cur = s & 1, par_prev = (s + 1) & 1;
    const uint32_t sb = smem_u32(sm);

    int* tok_s = (int*)(sm + S_TOK);
    if (which == 0 && tid < 128) tok_s[tid] = x[(m0 + tid) * T_ + s];
    __syncthreads();

    const __nv_bfloat16* __restrict__ Wh = which ? g_W1h : g_W0h;
    const __nv_bfloat16* __restrict__ Wl = which ? g_W1l : g_W0l;

    const int warp = tid >> 5, lane = tid & 31;
    const int wm = warp >> 2, wn = warp & 3;

    // loader: 512 threads cover 128 rows x 32 k in one pass per tile
    const int ldr = (tid >> 2);          // 0..127
    const int ldk = (tid & 3) * 8;       // 0/8/16/24

    auto load_chunk = [&](int c, int buf) {
        const int kb = c * 32;
        const uint32_t sbst = sb + buf * STAGE_B;
        const int r = ldr;
        const int kk = kb + ldk;
        const __nv_bfloat16 *pah, *pal;
        if (which) {
            if (kb < 512) {
                size_t o = (size_t)(m0 + r) * 512 + kk;
                pah = &g_h0h[par_cur][o]; pal = &g_h0l[par_cur][o];
            } else {
                size_t o = (size_t)(m0 + r) * 512 + kk - 512;
                pah = &g_h1h[par_prev][o]; pal = &g_h1l[par_prev][o];
            }
        } else {
            if (kb < 128) {
                size_t o = (size_t)tok_s[r] * 128 + kk;
                pah = &g_Eh[o]; pal = &g_El[o];
            } else {
                size_t o = (size_t)(m0 + r) * 512 + kk - 128;
                pah = &g_h0h[par_prev][o]; pal = &g_h0l[par_prev][o];
            }
        }
        const int dst = (r * LDA + ldk) * 2;
        cp16(sbst + S_AHI + dst, pah);
        cp16(sbst + S_ALO + dst, pal);
        size_t bo = (size_t)(col0 + r) * K + kk;
        cp16(sbst + S_BHI + dst, &Wh[bo]);
        cp16(sbst + S_BLO + dst, &Wl[bo]);
    };

    float acc[2][4][4];
#pragma unroll
    for (int i = 0; i < 2; i++)
#pragma unroll
        for (int q = 0; q < 4; q++)
#pragma unroll
            for (int r = 0; r < 4; r++) acc[i][q][r] = 0.f;

    // ldmatrix per-thread base addresses (stage 0)
    const int arow = wm * 32 + (lane & 15);
    const int ahalf = (lane >> 4) * 8;
    const uint32_t a_hi0 = sb + S_AHI + (arow * LDA + ahalf) * 2;
    const uint32_t a_lo0 = sb + S_ALO + (arow * LDA + ahalf) * 2;
    const int brow = wn * 32 + (lane & 7);
    const int bhalf = ((lane >> 3) & 1) * 8;
    const uint32_t b_hi0 = sb + S_BHI + (brow * LDA + bhalf) * 2;
    const uint32_t b_lo0 = sb + S_BLO + (brow * LDA + bhalf) * 2;

    load_chunk(0, 0); cp_commit();
    load_chunk(1, 1); cp_commit();

    int buf = 0;
    for (int c = 0; c < nch; c++) {
        if (c == nch - 1) cp_wait0(); else cp_wait1();
        __syncthreads();
        if (c + 2 < nch) {
            int nb = buf + 2; if (nb >= NSTAGE) nb -= NSTAGE;
            load_chunk(c + 2, nb);
            cp_commit();
        }
        const uint32_t so = (uint32_t)(buf * STAGE_B);
#pragma unroll
        for (int kk = 0; kk < 2; kk++) {
            const uint32_t koff = so + (uint32_t)(kk * 16 * 2);
            uint32_t af[2][4], bh[4][2], bl[4][2];
#pragma unroll
            for (int q = 0; q < 4; q++) {
                ldsm_x2(bh[q][0], bh[q][1], b_hi0 + koff + q * (8 * LDA * 2));
                ldsm_x2(bl[q][0], bl[q][1], b_lo0 + koff + q * (8 * LDA * 2));
            }
#pragma unroll
            for (int mf = 0; mf < 2; mf++)
                ldsm_x4(af[mf][0], af[mf][1], af[mf][2], af[mf][3],
                        a_hi0 + koff + mf * (16 * LDA * 2));
#pragma unroll
            for (int mf = 0; mf < 2; mf++)
#pragma unroll
                for (int q = 0; q < 4; q++) {
                    mma16816(acc[mf][q], af[mf], bh[q]);   // hi*hi
                    mma16816(acc[mf][q], af[mf], bl[q]);   // hi*lo
                }
#pragma unroll
            for (int mf = 0; mf < 2; mf++)
                ldsm_x4(af[mf][0], af[mf][1], af[mf][2], af[mf][3],
                        a_lo0 + koff + mf * (16 * LDA * 2));
#pragma unroll
            for (int mf = 0; mf < 2; mf++)
#pragma unroll
                for (int q = 0; q < 4; q++)
                    mma16816(acc[mf][q], af[mf], bh[q]);   // lo*hi
        }
        if (++buf == NSTAGE) buf = 0;
    }

    // ---- fused LSTM cell epilogue ----
    const float* __restrict__ bias = which ? g_b1i : g_b0i;
    float* __restrict__ Cc = which ? g_c1 : g_c0;
    __nv_bfloat16* __restrict__ Hh = which ? g_h1h[par_cur] : g_h0h[par_cur];
    __nv_bfloat16* __restrict__ Hl = which ? g_h1l[par_cur] : g_h0l[par_cur];

    const int p = lane & 3;
    const int rowb = lane >> 2;
    const int jbase = (col0 >> 2) + wn * 8;
    float bi[4][2];
#pragma unroll
    for (int g = 0; g < 4; g++) {
        bi[g][0] = bias[col0 + wn * 32 + g * 8 + 2 * p + 0];
        bi[g][1] = bias[col0 + wn * 32 + g * 8 + 2 * p + 1];
    }

#pragma unroll
    for (int mf = 0; mf < 2; mf++) {
#pragma unroll
        for (int r2 = 0; r2 < 2; r2++) {
            const int m = m0 + wm * 32 + mf * 16 + rowb + r2 * 8;
            const size_t cb = (size_t)m * 512 + jbase + 2 * p;
            float2 cold = *(const float2*)&Cc[cb];
            float hn[2], cn[2];
#pragma unroll
            for (int bit = 0; bit < 2; bit++) {
                const int ri = r2 * 2 + bit;
                float iv = acc[mf][0][ri] + bi[0][bit];
                float fv = acc[mf][1][ri] + bi[1][bit];
                float gv = acc[mf][2][ri] + bi[2][bit];
                float ov = acc[mf][3][ri] + bi[3][bit];
                float si = 1.f / (1.f + expf(-iv));
                float sf = 1.f / (1.f + expf(-fv));
                float tg = tanhf(gv);
                float so = 1.f / (1.f + expf(-ov));
                float co = bit ? cold.y : cold.x;
                cn[bit] = sf * co + si * tg;
                hn[bit] = so * tanhf(cn[bit]);
            }
            *(float2*)&Cc[cb] = make_float2(cn[0], cn[1]);
            __nv_bfloat16 h0b = __float2bfloat16(hn[0]);
            __nv_bfloat16 h1b = __float2bfloat16(hn[1]);
            __nv_bfloat16 l0b = __float2bfloat16(hn[0] - __bfloat162float(h0b));
            __nv_bfloat16 l1b = __float2bfloat16(hn[1] - __bfloat162float(h1b));
            uint32_t hp = (uint32_t)__bfloat16_as_ushort(h0b) |
                          ((uint32_t)__bfloat16_as_ushort(h1b) << 16);
            uint32_t lp = (uint32_t)__bfloat16_as_ushort(l0b) |
                          ((uint32_t)__bfloat16_as_ushort(l1b) << 16);
            *(uint32_t*)&Hh[cb] = hp;
            *(uint32_t*)&Hl[cb] = lp;
        }
    }
}

// ---------------- fc: 8 batches/block, warp w<8 handles batch b0+w ----------------
__device__ void fc_part(char* sm, int fid, int s, const int* __restrict__ x,
                        const float* __restrict__ Wfc, const float* __restrict__ bfc,
                        float* __restrict__ out) {
    const int tid = threadIdx.x;
    float* hs = (float*)sm;               // [8][512]
    float* lgs = (float*)(sm + 16384);    // [8][40]
    const int b0 = fid * 8;
    const int par = s & 1;
    for (int i = tid; i < 8 * 512; i += 512) {
        int b = i >> 9, k = i & 511;
        size_t idx = (size_t)(b0 + b) * 512 + k;
        hs[i] = __bfloat162float(g_h1h[par][idx]) + __bfloat162float(g_h1l[par][idx]);
    }
    __syncthreads();
    const int w = tid >> 5, lane = tid & 31;
    if (w < 8) {
        const int b = b0 + w;
        const float* hb = hs + w * 512;
        for (int v = 0; v < V_; v++) {
            float sum = 0.f;
#pragma unroll
            for (int kk = 0; kk < 16; kk++) {
                int k = lane + kk * 32;
                sum += hb[k] * Wfc[v * 512 + k];
            }
#pragma unroll
            for (int o = 16; o; o >>= 1) sum += __shfl_xor_sync(0xffffffffu, sum, o);
            if (lane == 0) lgs[w * 40 + v] = fmaxf(sum + bfc[v], 0.f);
        }
        __syncwarp();
        if (lane == 0) {
            float mx = -1e30f;
            for (int v = 0; v < V_; v++) mx = fmaxf(mx, lgs[w * 40 + v]);
            float se = 0.f;
            for (int v = 0; v < V_; v++) se += expf(lgs[w * 40 + v] - mx);
            lgs[w * 40 + 36] = mx;
            lgs[w * 40 + 37] = se;
            int tgt = x[b * T_ + s + 1];
            g_loss[b * TSTEPS + s] = (tgt == 0) ? 0.f : -lgs[w * 40 + tgt];
        }
        __syncwarp();
        for (int v = lane; v < V_; v += 32) {
            float pr = expf(lgs[w * 40 + v] - lgs[w * 40 + 36]) / lgs[w * 40 + 37];
            out[OFF_PROBS + ((size_t)b * TSTEPS + s) * V_ + v] = pr;
        }
    }
}

// ---------------- step kernel ----------------
// mode 0: gemm0(step 0), grid 64
// mode 1: grid 128 = gemm1(t)[0..63] + [gemm0(t+1) then fc(t-1)][64..127]
// mode 2: fc(126), grid 64
__global__ __launch_bounds__(512, 1) void step_kernel(int t, int mode,
        const int* __restrict__ x, const float* __restrict__ Wfc,
        const float* __restrict__ bfc, float* __restrict__ out) {
    extern __shared__ char sm[];
    int bid = blockIdx.x;
    if (mode == 0) { gemm_part(sm, bid, 0, 0, x); return; }
    if (mode == 2) { fc_part(sm, bid, 126, x, Wfc, bfc, out); return; }
    if (bid < 64) {
        gemm_part(sm, bid, 1, t, x);
    } else {
        if (t < 126) gemm_part(sm, bid - 64, 0, t + 1, x);
        if (t > 0) {
            __syncthreads();
            fc_part(sm, bid - 64, t - 1, x, Wfc, bfc, out);
        }
    }
}

// ---------------- prologue ----------------
__global__ void prep_kernel(const float* __restrict__ Wih0, const float* __restrict__ Whh0,
                            const float* __restrict__ Wih1, const float* __restrict__ Whh1,
                            const float* __restrict__ bi0, const float* __restrict__ bh0,
                            const float* __restrict__ bi1, const float* __restrict__ bh1,
                            const float* __restrict__ tab) {
    int i = blockIdx.x * 256 + threadIdx.x;
    if (i < 2048 * 1024) {
        int np = i >> 10, k = i & 1023;
        int r = ((np >> 3) & 3) * 512 + (np >> 5) * 8 + (np & 7);
        float v = (k < 512) ? Wih1[r * 512 + k] : Whh1[r * 512 + k - 512];
        __nv_bfloat16 hi = __float2bfloat16(v);
        g_W1h[i] = hi;
        g_W1l[i] = __float2bfloat16(v - __bfloat162float(hi));
    }
    if (i < 2048 * 640) {
        int np = i / 640, k = i - np * 640;
        int r = ((np >> 3) & 3) * 512 + (np >> 5) * 8 + (np & 7);
        float v = (k < 128) ? Wih0[r * 128 + k] : Whh0[r * 512 + k - 128];
        __nv_bfloat16 hi = __float2bfloat16(v);
        g_W0h[i] = hi;
        g_W0l[i] = __float2bfloat16(v - __bfloat162float(hi));
    }
    if (i < 36 * 128) {
        float v = tab[i];
        __nv_bfloat16 hi = __float2bfloat16(v);
        g_Eh[i] = hi;
        g_El[i] = __float2bfloat16(v - __bfloat162float(hi));
    }
    if (i < 2048) {
        int r = ((i >> 3) & 3) * 512 + (i >> 5) * 8 + (i & 7);
        g_b0i[i] = bi0[r] + bh0[r];
        g_b1i[i] = bi1[r] + bh1[r];
    }
    if (i < 512 * 512) {
        g_c0[i] = 0.f; g_c1[i] = 0.f;
        __nv_bfloat16 z = __float2bfloat16(0.f);
        g_h0h[1][i] = z; g_h0l[1][i] = z;
        g_h1h[1][i] = z; g_h1l[1][i] = z;
    }
}

// ---------------- embedding output ----------------
__global__ void embed_kernel(const int* __restrict__ x, const float* __restrict__ tab,
                             float* __restrict__ out_emb) {
    int idx = blockIdx.x * 256 + threadIdx.x;
    if (idx >= (int)(EMB_N / 4)) return;
    int e4 = idx & 31;
    int bt = idx >> 5;
    int tok = x[bt];
    float4 v = reinterpret_cast<const float4*>(tab)[tok * 32 + e4];
    reinterpret_cast<float4*>(out_emb)[idx] = v;
}

// ---------------- finalize ----------------
__global__ void finalize_kernel(const int* __restrict__ x, float* __restrict__ out) {
    __shared__ float red[B_];
    int b = threadIdx.x;
    float s = 0.f;
    for (int t = 0; t < TSTEPS; t++) s += g_loss[b * TSTEPS + t];
    int len = 0;
    for (int t = 0; t < T_; t++) len += (x[b * T_ + t] != 0);
    float sl = s / (float)len;
    out[OFF_SL + b] = sl;
    red[b] = sl;
    __syncthreads();
    for (int st = 256; st > 0; st >>= 1) {
        if (b < st) red[b] += red[b + st];
        __syncthreads();
    }
    if (b == 0) out[OFF_MEAN] = red[0] / (float)B_;
}

// ---------------- launch ----------------
extern "C" void kernel_launch(void* const* d_in, const int* in_sizes, int n_in,
                              void* d_out, int out_size) {
    const int*   x    = (const int*)  d_in[0];
    const float* tab  = (const float*)d_in[1];
    const float* Wih0 = (const float*)d_in[2];
    const float* Whh0 = (const float*)d_in[3];
    const float* bih0 = (const float*)d_in[4];
    const float* bhh0 = (const float*)d_in[5];
    const float* Wih1 = (const float*)d_in[6];
    const float* Whh1 = (const float*)d_in[7];
    const float* bih1 = (const float*)d_in[8];
    const float* bhh1 = (const float*)d_in[9];
    const float* Wfc  = (const float*)d_in[10];
    const float* bfc  = (const float*)d_in[11];
    float* out = (float*)d_out;

    cudaFuncSetAttribute(step_kernel, cudaFuncAttributeMaxDynamicSharedMemorySize, SMEM_BYTES);

    prep_kernel<<<(2048 * 1024) / 256, 256>>>(Wih0, Whh0, Wih1, Whh1,
                                              bih0, bhh0, bih1, bhh1, tab);
    embed_kernel<<<(int)((EMB_N / 4 + 255) / 256), 256>>>(x, tab, out + OFF_EMB);

    step_kernel<<<64, 512, SMEM_BYTES>>>(0, 0, x, Wfc, bfc, out);
    for (int t = 0; t < TSTEPS; t++)
        step_kernel<<<128, 512, SMEM_BYTES>>>(t, 1, x, Wfc, bfc, out);
    step_kernel<<<64, 512, SMEM_BYTES>>>(0, 2, x, Wfc, bfc, out);
    finalize_kernel<<<1, B_>>>(x, out);
}

// round 9
// speedup vs baseline: 3.8471x; 1.0784x over previous
#include <cuda_runtime.h>
#include <cuda_bf16.h>
#include <math.h>
#include <stdint.h>

#define B_      512
#define T_      128
#define V_      36
#define E_      128
#define H_      512
#define TSTEPS  127

#define PROBS_N  ((size_t)B_ * TSTEPS * V_)
#define EMB_N    ((size_t)B_ * T_ * E_)
#define OFF_PROBS 0
#define OFF_EMB   (PROBS_N)
#define OFF_SL    (OFF_EMB + EMB_N)
#define OFF_MEAN  (OFF_SL + B_)

// ---------------- device scratch (no allocation) ----------------
// Weights split bf16 hi/lo. Column interleave: out-col c <-> orig gate row
//   r = ((c>>3)&3)*512 + (c>>5)*8 + (c&7)
__device__ __nv_bfloat16 g_W0h[2048 * 640];
__device__ __nv_bfloat16 g_W0l[2048 * 640];
__device__ __nv_bfloat16 g_W1h[2048 * 1024];
__device__ __nv_bfloat16 g_W1l[2048 * 1024];
__device__ float g_b0i[2048], g_b1i[2048];
__device__ __nv_bfloat16 g_Eh[36 * 128], g_El[36 * 128];
__device__ __nv_bfloat16 g_h0h[2][512 * 512], g_h0l[2][512 * 512];
__device__ __nv_bfloat16 g_h1h[2][512 * 512], g_h1l[2][512 * 512];
__device__ float g_c0[512 * 512], g_c1[512 * 512];
__device__ float g_loss[512 * TSTEPS];

// ---------------- smem layout (bytes) ----------------
// Per stage: 4 tiles [128 rows][64 k] bf16, row stride 72 elems (144B) -> conflict-free ldsm
#define LDA2     72
#define TILE_B2  (128 * LDA2 * 2)            // 18432
#define S_AHI    0
#define S_ALO    (1 * TILE_B2)
#define S_BHI    (2 * TILE_B2)
#define S_BLO    (3 * TILE_B2)
#define STAGE_B  (4 * TILE_B2)               // 73728
#define NSTAGE   2
#define S_TOK    (NSTAGE * STAGE_B)          // 147456
#define SMEM_BYTES (S_TOK + 512)             // 147968

// ---------------- PTX helpers ----------------
__device__ __forceinline__ uint32_t smem_u32(const void* p) {
    uint32_t a;
    asm("{ .reg .u64 t; cvta.to.shared.u64 t, %1; cvt.u32.u64 %0, t; }" : "=r"(a) : "l"(p));
    return a;
}
__device__ __forceinline__ void cp16(uint32_t dst, const void* src) {
    asm volatile("cp.async.cg.shared.global [%0], [%1], 16;" :: "r"(dst), "l"(src));
}
__device__ __forceinline__ void cp_commit() { asm volatile("cp.async.commit_group;" ::: "memory"); }
__device__ __forceinline__ void cp_wait0()  { asm volatile("cp.async.wait_group 0;" ::: "memory"); }
__device__ __forceinline__ void cp_wait1()  { asm volatile("cp.async.wait_group 1;" ::: "memory"); }
__device__ __forceinline__ void ldsm_x4(uint32_t* r, uint32_t addr) {
    asm volatile("ldmatrix.sync.aligned.m8n8.x4.shared.b16 {%0,%1,%2,%3}, [%4];"
                 : "=r"(r[0]), "=r"(r[1]), "=r"(r[2]), "=r"(r[3]) : "r"(addr));
}
__device__ __forceinline__ void mma16816(float* d, const uint32_t* a, const uint32_t* b) {
    asm volatile(
        "mma.sync.aligned.m16n8k16.row.col.f32.bf16.bf16.f32 "
        "{%0,%1,%2,%3}, {%4,%5,%6,%7}, {%8,%9}, {%0,%1,%2,%3};"
        : "+f"(d[0]), "+f"(d[1]), "+f"(d[2]), "+f"(d[3])
        : "r"(a[0]), "r"(a[1]), "r"(a[2]), "r"(a[3]), "r"(b[0]), "r"(b[1]));
}

// ---------------- GEMM + fused LSTM cell (512 thr, 16 warps 4x4, warp tile 32x32, BK=64) ----
// which==0: step s: A = [emb(x[:,s]) | h0[par_prev]], K=640,  writes h0[par_cur], c0
// which==1: step s: A = [h0[par_cur] | h1[par_prev]], K=1024, writes h1[par_cur], c1
__device__ void gemm_part(char* sm, int tileid, int which, int s, const int* __restrict__ x) {
    const int tid = threadIdx.x;
    const int m0 = (tileid >> 4) * 128;
    const int col0 = (tileid & 15) * 128;
    const int K = which ? 1024 : 640;
    const int nch = K / 64;
    const int par_cur = s & 1, par_prev = (s + 1) & 1;
    const uint32_t sb = smem_u32(sm);

    int* tok_s = (int*)(sm + S_TOK);
    if (which == 0 && tid < 128) tok_s[tid] = x[(m0 + tid) * T_ + s];
    __syncthreads();

    const __nv_bfloat16* __restrict__ Wh = which ? g_W1h : g_W0h;
    const __nv_bfloat16* __restrict__ Wl = which ? g_W1l : g_W0l;

    const int warp = tid >> 5, lane = tid & 31;
    const int wm = warp >> 2, wn = warp & 3;

    // loader: 512 threads cover 64 rows x 64 k per pass; 2 passes = 128 rows
    const int ldr = (tid >> 3);          // 0..63
    const int ldk = (tid & 7) * 8;       // 0..56

    auto load_chunk = [&](int c, int buf) {
        const int kb = c * 64;
        const uint32_t sbst = sb + buf * STAGE_B;
#pragma unroll
        for (int it = 0; it < 2; it++) {
            const int r = it * 64 + ldr;
            const int kk = kb + ldk;
            const __nv_bfloat16 *pah, *pal;
            if (which) {
                if (kb < 512) {
                    size_t o = (size_t)(m0 + r) * 512 + kk;
                    pah = &g_h0h[par_cur][o]; pal = &g_h0l[par_cur][o];
                } else {
                    size_t o = (size_t)(m0 + r) * 512 + kk - 512;
                    pah = &g_h1h[par_prev][o]; pal = &g_h1l[par_prev][o];
                }
            } else {
                if (kb < 128) {
                    size_t o = (size_t)tok_s[r] * 128 + kk;
                    pah = &g_Eh[o]; pal = &g_El[o];
                } else {
                    size_t o = (size_t)(m0 + r) * 512 + kk - 128;
                    pah = &g_h0h[par_prev][o]; pal = &g_h0l[par_prev][o];
                }
            }
            const int dst = (r * LDA2 + ldk) * 2;
            cp16(sbst + S_AHI + dst, pah);
            cp16(sbst + S_ALO + dst, pal);
            size_t bo = (size_t)(col0 + r) * K + kk;
            cp16(sbst + S_BHI + dst, &Wh[bo]);
            cp16(sbst + S_BLO + dst, &Wl[bo]);
        }
    };

    float acc[2][4][4];
#pragma unroll
    for (int i = 0; i < 2; i++)
#pragma unroll
        for (int q = 0; q < 4; q++)
#pragma unroll
            for (int r = 0; r < 4; r++) acc[i][q][r] = 0.f;

    // ldmatrix per-thread base addresses (stage 0)
    const int arow = wm * 32 + (lane & 15);
    const int ahalf = (lane >> 4) * 8;                 // A: x4 = 2 m-halves x 2 k-halves
    const uint32_t a_hi0 = sb + S_AHI + (arow * LDA2 + ahalf) * 2;
    const uint32_t a_lo0 = sb + S_ALO + (arow * LDA2 + ahalf) * 2;
    const int brow = wn * 32 + (lane & 7);
    const int bhalf = (lane >> 3) * 8;                 // B: x4 = 4 consecutive k-halves
    const uint32_t b_hi0 = sb + S_BHI + (brow * LDA2 + bhalf) * 2;
    const uint32_t b_lo0 = sb + S_BLO + (brow * LDA2 + bhalf) * 2;

    load_chunk(0, 0); cp_commit();

    int buf = 0;
    for (int c = 0; c < nch; c++) {
        if (c + 1 < nch) {
            load_chunk(c + 1, buf ^ 1);
            cp_commit();
            cp_wait1();
        } else {
            cp_wait0();
        }
        __syncthreads();
        const uint32_t so = (uint32_t)(buf * STAGE_B);
#pragma unroll
        for (int kh = 0; kh < 2; kh++) {
            const uint32_t koff = so + (uint32_t)(kh * 32 * 2);   // 32 k-elements per half
            uint32_t bh[4][4], bl[4][4], afh[2][2][4], afl[2][2][4];
#pragma unroll
            for (int q = 0; q < 4; q++) {
                ldsm_x4(bh[q], b_hi0 + koff + q * (8 * LDA2 * 2));
                ldsm_x4(bl[q], b_lo0 + koff + q * (8 * LDA2 * 2));
            }
#pragma unroll
            for (int ks = 0; ks < 2; ks++)
#pragma unroll
                for (int mf = 0; mf < 2; mf++)
                    ldsm_x4(afh[ks][mf], a_hi0 + koff + ks * 32 + mf * (16 * LDA2 * 2));
            // pass 1: hi*hi  (8 independent acc chains per ks)
#pragma unroll
            for (int ks = 0; ks < 2; ks++)
#pragma unroll
                for (int mf = 0; mf < 2; mf++)
#pragma unroll
                    for (int q = 0; q < 4; q++)
                        mma16816(acc[mf][q], afh[ks][mf], &bh[q][ks * 2]);
            // pass 2: hi*lo
#pragma unroll
            for (int ks = 0; ks < 2; ks++)
#pragma unroll
                for (int mf = 0; mf < 2; mf++)
#pragma unroll
                    for (int q = 0; q < 4; q++)
                        mma16816(acc[mf][q], afh[ks][mf], &bl[q][ks * 2]);
            // load A-lo, pass 3: lo*hi
#pragma unroll
            for (int ks = 0; ks < 2; ks++)
#pragma unroll
                for (int mf = 0; mf < 2; mf++)
                    ldsm_x4(afl[ks][mf], a_lo0 + koff + ks * 32 + mf * (16 * LDA2 * 2));
#pragma unroll
            for (int ks = 0; ks < 2; ks++)
#pragma unroll
                for (int mf = 0; mf < 2; mf++)
#pragma unroll
                    for (int q = 0; q < 4; q++)
                        mma16816(acc[mf][q], afl[ks][mf], &bh[q][ks * 2]);
        }
        __syncthreads();
        buf ^= 1;
    }

    // ---- fused LSTM cell epilogue ----
    const float* __restrict__ bias = which ? g_b1i : g_b0i;
    float* __restrict__ Cc = which ? g_c1 : g_c0;
    __nv_bfloat16* __restrict__ Hh = which ? g_h1h[par_cur] : g_h0h[par_cur];
    __nv_bfloat16* __restrict__ Hl = which ? g_h1l[par_cur] : g_h0l[par_cur];

    const int p = lane & 3;
    const int rowb = lane >> 2;
    const int jbase = (col0 >> 2) + wn * 8;
    float bi[4][2];
#pragma unroll
    for (int g = 0; g < 4; g++) {
        bi[g][0] = bias[col0 + wn * 32 + g * 8 + 2 * p + 0];
        bi[g][1] = bias[col0 + wn * 32 + g * 8 + 2 * p + 1];
    }

#pragma unroll
    for (int mf = 0; mf < 2; mf++) {
#pragma unroll
        for (int r2 = 0; r2 < 2; r2++) {
            const int m = m0 + wm * 32 + mf * 16 + rowb + r2 * 8;
            const size_t cb = (size_t)m * 512 + jbase + 2 * p;
            float2 cold = *(const float2*)&Cc[cb];
            float hn[2], cn[2];
#pragma unroll
            for (int bit = 0; bit < 2; bit++) {
                const int ri = r2 * 2 + bit;
                float iv = acc[mf][0][ri] + bi[0][bit];
                float fv = acc[mf][1][ri] + bi[1][bit];
                float gv = acc[mf][2][ri] + bi[2][bit];
                float ov = acc[mf][3][ri] + bi[3][bit];
                float si = 1.f / (1.f + expf(-iv));
                float sf = 1.f / (1.f + expf(-fv));
                float tg = tanhf(gv);
                float so = 1.f / (1.f + expf(-ov));
                float co = bit ? cold.y : cold.x;
                cn[bit] = sf * co + si * tg;
                hn[bit] = so * tanhf(cn[bit]);
            }
            *(float2*)&Cc[cb] = make_float2(cn[0], cn[1]);
            __nv_bfloat16 h0b = __float2bfloat16(hn[0]);
            __nv_bfloat16 h1b = __float2bfloat16(hn[1]);
            __nv_bfloat16 l0b = __float2bfloat16(hn[0] - __bfloat162float(h0b));
            __nv_bfloat16 l1b = __float2bfloat16(hn[1] - __bfloat162float(h1b));
            uint32_t hp = (uint32_t)__bfloat16_as_ushort(h0b) |
                          ((uint32_t)__bfloat16_as_ushort(h1b) << 16);
            uint32_t lp = (uint32_t)__bfloat16_as_ushort(l0b) |
                          ((uint32_t)__bfloat16_as_ushort(l1b) << 16);
            *(uint32_t*)&Hh[cb] = hp;
            *(uint32_t*)&Hl[cb] = lp;
        }
    }
}

// ---------------- fc: 8 batches/block, warp w<8 handles batch b0+w ----------------
__device__ void fc_part(char* sm, int fid, int s, const int* __restrict__ x,
                        const float* __restrict__ Wfc, const float* __restrict__ bfc,
                        float* __restrict__ out) {
    const int tid = threadIdx.x;
    float* hs = (float*)sm;               // [8][512]
    float* lgs = (float*)(sm + 16384);    // [8][40]
    const int b0 = fid * 8;
    const int par = s & 1;
    for (int i = tid; i < 8 * 512; i += 512) {
        int b = i >> 9, k = i & 511;
        size_t idx = (size_t)(b0 + b) * 512 + k;
        hs[i] = __bfloat162float(g_h1h[par][idx]) + __bfloat162float(g_h1l[par][idx]);
    }
    __syncthreads();
    const int w = tid >> 5, lane = tid & 31;
    if (w < 8) {
        const int b = b0 + w;
        const float* hb = hs + w * 512;
        for (int v = 0; v < V_; v++) {
            float sum = 0.f;
#pragma unroll
            for (int kk = 0; kk < 16; kk++) {
                int k = lane + kk * 32;
                sum += hb[k] * Wfc[v * 512 + k];
            }
#pragma unroll
            for (int o = 16; o; o >>= 1) sum += __shfl_xor_sync(0xffffffffu, sum, o);
            if (lane == 0) lgs[w * 40 + v] = fmaxf(sum + bfc[v], 0.f);
        }
        __syncwarp();
        if (lane == 0) {
            float mx = -1e30f;
            for (int v = 0; v < V_; v++) mx = fmaxf(mx, lgs[w * 40 + v]);
            float se = 0.f;
            for (int v = 0; v < V_; v++) se += expf(lgs[w * 40 + v] - mx);
            lgs[w * 40 + 36] = mx;
            lgs[w * 40 + 37] = se;
            int tgt = x[b * T_ + s + 1];
            g_loss[b * TSTEPS + s] = (tgt == 0) ? 0.f : -lgs[w * 40 + tgt];
        }
        __syncwarp();
        for (int v = lane; v < V_; v += 32) {
            float pr = expf(lgs[w * 40 + v] - lgs[w * 40 + 36]) / lgs[w * 40 + 37];
            out[OFF_PROBS + ((size_t)b * TSTEPS + s) * V_ + v] = pr;
        }
    }
}

// ---------------- step kernel ----------------
// mode 0: gemm0(step 0), grid 64
// mode 1: grid 128 = gemm1(t)[0..63] + [gemm0(t+1) then fc(t-1)][64..127]
// mode 2: fc(126), grid 64
__global__ __launch_bounds__(512, 1) void step_kernel(int t, int mode,
        const int* __restrict__ x, const float* __restrict__ Wfc,
        const float* __restrict__ bfc, float* __restrict__ out) {
    extern __shared__ char sm[];
    int bid = blockIdx.x;
    if (mode == 0) { gemm_part(sm, bid, 0, 0, x); return; }
    if (mode == 2) { fc_part(sm, bid, 126, x, Wfc, bfc, out); return; }
    if (bid < 64) {
        gemm_part(sm, bid, 1, t, x);
    } else {
        if (t < 126) gemm_part(sm, bid - 64, 0, t + 1, x);
        if (t > 0) {
            __syncthreads();
            fc_part(sm, bid - 64, t - 1, x, Wfc, bfc, out);
        }
    }
}

// ---------------- prologue ----------------
__global__ void prep_kernel(const float* __restrict__ Wih0, const float* __restrict__ Whh0,
                            const float* __restrict__ Wih1, const float* __restrict__ Whh1,
                            const float* __restrict__ bi0, const float* __restrict__ bh0,
                            const float* __restrict__ bi1, const float* __restrict__ bh1,
                            const float* __restrict__ tab) {
    int i = blockIdx.x * 256 + threadIdx.x;
    if (i < 2048 * 1024) {
        int np = i >> 10, k = i & 1023;
        int r = ((np >> 3) & 3) * 512 + (np >> 5) * 8 + (np & 7);
        float v = (k < 512) ? Wih1[r * 512 + k] : Whh1[r * 512 + k - 512];
        __nv_bfloat16 hi = __float2bfloat16(v);
        g_W1h[i] = hi;
        g_W1l[i] = __float2bfloat16(v - __bfloat162float(hi));
    }
    if (i < 2048 * 640) {
        int np = i / 640, k = i - np * 640;
        int r = ((np >> 3) & 3) * 512 + (np >> 5) * 8 + (np & 7);
        float v = (k < 128) ? Wih0[r * 128 + k] : Whh0[r * 512 + k - 128];
        __nv_bfloat16 hi = __float2bfloat16(v);
        g_W0h[i] = hi;
        g_W0l[i] = __float2bfloat16(v - __bfloat162float(hi));
    }
    if (i < 36 * 128) {
        float v = tab[i];
        __nv_bfloat16 hi = __float2bfloat16(v);
        g_Eh[i] = hi;
        g_El[i] = __float2bfloat16(v - __bfloat162float(hi));
    }
    if (i < 2048) {
        int r = ((i >> 3) & 3) * 512 + (i >> 5) * 8 + (i & 7);
        g_b0i[i] = bi0[r] + bh0[r];
        g_b1i[i] = bi1[r] + bh1[r];
    }
    if (i < 512 * 512) {
        g_c0[i] = 0.f; g_c1[i] = 0.f;
        __nv_bfloat16 z = __float2bfloat16(0.f);
        g_h0h[1][i] = z; g_h0l[1][i] = z;
        g_h1h[1][i] = z; g_h1l[1][i] = z;
    }
}

// ---------------- embedding output ----------------
__global__ void embed_kernel(const int* __restrict__ x, const float* __restrict__ tab,
                             float* __restrict__ out_emb) {
    int idx = blockIdx.x * 256 + threadIdx.x;
    if (idx >= (int)(EMB_N / 4)) return;
    int e4 = idx & 31;
    int bt = idx >> 5;
    int tok = x[bt];
    float4 v = reinterpret_cast<const float4*>(tab)[tok * 32 + e4];
    reinterpret_cast<float4*>(out_emb)[idx] = v;
}

// ---------------- finalize ----------------
__global__ void finalize_kernel(const int* __restrict__ x, float* __restrict__ out) {
    __shared__ float red[B_];
    int b = threadIdx.x;
    float s = 0.f;
    for (int t = 0; t < TSTEPS; t++) s += g_loss[b * TSTEPS + t];
    int len = 0;
    for (int t = 0; t < T_; t++) len += (x[b * T_ + t] != 0);
    float sl = s / (float)len;
    out[OFF_SL + b] = sl;
    red[b] = sl;
    __syncthreads();
    for (int st = 256; st > 0; st >>= 1) {
        if (b < st) red[b] += red[b + st];
        __syncthreads();
    }
    if (b == 0) out[OFF_MEAN] = red[0] / (float)B_;
}

// ---------------- launch ----------------
extern "C" void kernel_launch(void* const* d_in, const int* in_sizes, int n_in,
                              void* d_out, int out_size) {
    const int*   x    = (const int*)  d_in[0];
    const float* tab  = (const float*)d_in[1];
    const float* Wih0 = (const float*)d_in[2];
    const float* Whh0 = (const float*)d_in[3];
    const float* bih0 = (const float*)d_in[4];
    const float* bhh0 = (const float*)d_in[5];
    const float* Wih1 = (const float*)d_in[6];
    const float* Whh1 = (const float*)d_in[7];
    const float* bih1 = (const float*)d_in[8];
    const float* bhh1 = (const float*)d_in[9];
    const float* Wfc  = (const float*)d_in[10];
    const float* bfc  = (const float*)d_in[11];
    float* out = (float*)d_out;

    cudaFuncSetAttribute(step_kernel, cudaFuncAttributeMaxDynamicSharedMemorySize, SMEM_BYTES);

    prep_kernel<<<(2048 * 1024) / 256, 256>>>(Wih0, Whh0, Wih1, Whh1,
                                              bih0, bhh0, bih1, bhh1, tab);
    embed_kernel<<<(int)((EMB_N / 4 + 255) / 256), 256>>>(x, tab, out + OFF_EMB);

    step_kernel<<<64, 512, SMEM_BYTES>>>(0, 0, x, Wfc, bfc, out);
    for (int t = 0; t < TSTEPS; t++)
        step_kernel<<<128, 512, SMEM_BYTES>>>(t, 1, x, Wfc, bfc, out);
    step_kernel<<<64, 512, SMEM_BYTES>>>(0, 2, x, Wfc, bfc, out);
    finalize_kernel<<<1, B_>>>(x, out);
}